// round 10
// baseline (speedup 1.0000x reference)
#include <cuda_runtime.h>
#include <math.h>
#include <stdint.h>

// ---------------- problem constants ----------------
#define DIMN   3072
#define HEADS  24
#define HD     128
#define S_HID  3072
#define S_ENC  512
#define SEQ    3584          // S_ENC + S_HID
#define CONDN  1024
#define RANKN  64
#define BLOCKL 2048          // S_HID - CONDN
#define NROWS_C (SEQ - S_ENC - CONDN)   // 2048 fully-masked query rows
#define KSPLIT 16            // split-K for LoRA down-proj
static const float ATTN_SCALE = 0.08838834764831843f; // 1/sqrt(128)

// ---------------- device scratch (no allocs allowed) ----------------
__device__ float g_Pq[(size_t)S_HID * DIMN];
__device__ float g_Pk[(size_t)S_HID * DIMN];
__device__ float g_Pv[(size_t)S_HID * DIMN];
__device__ float g_Eq[(size_t)S_ENC * DIMN];
__device__ float g_Ek[(size_t)S_ENC * DIMN];
__device__ float g_Ev[(size_t)S_ENC * DIMN];
__device__ float g_Dt[(size_t)CONDN * RANKN];
__device__ float g_DtP[(size_t)KSPLIT * CONDN * RANKN];  // split-K partials
__device__ float g_Q [(size_t)HEADS * SEQ * HD];
__device__ float g_K [(size_t)HEADS * SEQ * HD];
__device__ float g_Vt[(size_t)HEADS * HD * SEQ];      // V transposed: [h][d][s]
__device__ float g_SA[(size_t)HEADS * S_ENC * SEQ];   // encoder-query scores
__device__ float g_SB[(size_t)HEADS * CONDN * CONDN]; // cond-block scores
__device__ float g_AO[(size_t)(S_ENC + CONDN) * DIMN];// attention out rows 0..1535
__device__ float g_mean[DIMN];
__device__ float g_vec [DIMN];
// RNA-rounded (tf32-representable) operand copies
__device__ float g_rh [(size_t)S_HID * DIMN];
__device__ float g_re [(size_t)S_ENC * DIMN];
__device__ float g_rWq [(size_t)DIMN * DIMN];
__device__ float g_rWk [(size_t)DIMN * DIMN];
__device__ float g_rWv [(size_t)DIMN * DIMN];
__device__ float g_rWqa[(size_t)DIMN * DIMN];
__device__ float g_rWka[(size_t)DIMN * DIMN];
__device__ float g_rWva[(size_t)DIMN * DIMN];
__device__ float g_rWo [(size_t)DIMN * DIMN];
__device__ float g_rWoa[(size_t)DIMN * DIMN];
__device__ float g_rdn[3][(size_t)RANKN * DIMN];
__device__ float g_rup[3][(size_t)DIMN * RANKN];

// ---------------- helpers ----------------
__device__ __forceinline__ uint32_t f2tf(float f) {
    uint32_t u;
    asm("cvt.rna.tf32.f32 %0, %1;" : "=r"(u) : "f"(f));
    return u;
}
__device__ __forceinline__ float rndf(float x) { return __uint_as_float(f2tf(x)); }

__device__ __forceinline__ void cpasync16(float* dst, const float* src, bool pred) {
    uint32_t d = (uint32_t)__cvta_generic_to_shared(dst);
    int sz = pred ? 16 : 0;   // src-size 0 => zero-fill, no memory access
    asm volatile("cp.async.cg.shared.global [%0], [%1], 16, %2;\n"
                 :: "r"(d), "l"(src), "r"(sz));
}

__device__ __forceinline__ void mma_tf32(float* c, const uint32_t* a, const uint32_t* b) {
    asm volatile(
        "mma.sync.aligned.m16n8k8.row.col.f32.tf32.tf32.f32 "
        "{%0,%1,%2,%3}, {%4,%5,%6,%7}, {%8,%9}, {%0,%1,%2,%3};\n"
        : "+f"(c[0]), "+f"(c[1]), "+f"(c[2]), "+f"(c[3])
        : "r"(a[0]), "r"(a[1]), "r"(a[2]), "r"(a[3]), "r"(b[0]), "r"(b[1]));
}

// ---------------- tf32 tensor-core GEMM (operands pre-rounded to tf32) ----------------
// C = alpha * A[M,K] * B[N,K]^T (+bias, +beta*C).  A,B row-major, leading dims
// lda/ldb; batch via blockIdx.z with strides sA/sB/sC (also used for split-K).
// All GEMM inputs MUST already be tf32-representable (RNA-rounded); the inner
// loop feeds raw fp32 bits to the MMA with no CVT.
#define BK 16
#define ASTR 20   // smem row stride (floats)

template <int TBM, int TBN, int THREADS, int NSTAGE, int MT, int OCC, bool RND>
__global__ __launch_bounds__(THREADS, OCC)
void gemm_tf32(const float* __restrict__ A, const float* __restrict__ B,
               const float* __restrict__ bias, float* __restrict__ C,
               int M, int N, int K, int lda, int ldb, int ldc,
               long long sA, long long sB, long long sC,
               float alpha, const float* __restrict__ alpha_ptr, float beta)
{
    constexpr int PF = NSTAGE - 1;
    extern __shared__ float smem[];
    float* As = smem;                          // [NSTAGE][TBM][ASTR]
    float* Bs = smem + NSTAGE * TBM * ASTR;    // [NSTAGE][TBN][ASTR]

    const float* Ab = A + (long long)blockIdx.z * sA;
    const float* Bb = B + (long long)blockIdx.z * sB;
    float*       Cb = C + (long long)blockIdx.z * sC;

    const int m0 = blockIdx.y * TBM;
    const int n0 = blockIdx.x * TBN;
    const int tid  = threadIdx.x;
    const int lane = tid & 31;
    const int warp = tid >> 5;
    const int wm = (warp & 1) * (MT * 16);  // 2 m-warps
    const int wn = (warp >> 1) * 32;        // TBN/32 n-warps
    const int g  = lane >> 2;               // groupID
    const int tg = lane & 3;                // thread-in-group

    float c[MT][4][4];
#pragma unroll
    for (int i = 0; i < MT; i++)
#pragma unroll
        for (int j = 0; j < 4; j++)
#pragma unroll
            for (int r = 0; r < 4; r++) c[i][j][r] = 0.f;

    const int nk = K / BK;

    const int lrow = tid >> 2;              // 0..THREADS/4-1
    const int lkc  = (tid & 3) << 2;        // 0,4,8,12
    constexpr int RJUMP = THREADS / 4;

    auto load_tile = [&](int k0, int buf) {
        float* Ad = As + buf * TBM * ASTR;
        float* Bd = Bs + buf * TBN * ASTR;
#pragma unroll
        for (int j = 0; j < TBM / RJUMP; j++) {
            const int row = lrow + j * RJUMP;
            cpasync16(Ad + row * ASTR + lkc,
                      Ab + (long long)(m0 + row) * lda + k0 + lkc,
                      (m0 + row) < M);
        }
#pragma unroll
        for (int j = 0; j < TBN / RJUMP; j++) {
            const int row = lrow + j * RJUMP;
            cpasync16(Bd + row * ASTR + lkc,
                      Bb + (long long)(n0 + row) * ldb + k0 + lkc,
                      (n0 + row) < N);
        }
        asm volatile("cp.async.commit_group;\n");
    };

    for (int s = 0; s < PF; s++) {
        if (s < nk) load_tile(s * BK, s);
        else        asm volatile("cp.async.commit_group;\n");
    }

    for (int it = 0; it < nk; it++) {
        if (it + PF < nk) load_tile((it + PF) * BK, (it + PF) % NSTAGE);
        else              asm volatile("cp.async.commit_group;\n");
        asm volatile("cp.async.wait_group %0;\n" :: "n"(PF));
        __syncthreads();

        const int buf = it % NSTAGE;
        const float* Ac = As + buf * TBM * ASTR;
        const float* Bc = Bs + buf * TBN * ASTR;

#pragma unroll
        for (int ks = 0; ks < BK; ks += 8) {
            uint32_t bf[4][2];
#pragma unroll
            for (int nt = 0; nt < 4; nt++) {
                const float* bp = Bc + (wn + nt * 8 + g) * ASTR + ks + tg;
                bf[nt][0] = __float_as_uint(bp[0]);
                bf[nt][1] = __float_as_uint(bp[4]);
            }
            uint32_t af[MT][4];
#pragma unroll
            for (int mt = 0; mt < MT; mt++) {
                const float* ap = Ac + (wm + mt * 16 + g) * ASTR + ks + tg;
                af[mt][0] = __float_as_uint(ap[0]);
                af[mt][1] = __float_as_uint(ap[8 * ASTR]);
                af[mt][2] = __float_as_uint(ap[4]);
                af[mt][3] = __float_as_uint(ap[8 * ASTR + 4]);
            }
#pragma unroll
            for (int mt = 0; mt < MT; mt++)
#pragma unroll
                for (int nt = 0; nt < 4; nt++)
                    mma_tf32(c[mt][nt], af[mt], bf[nt]);
        }
        __syncthreads();
    }

    float aE = alpha;
    if (alpha_ptr) aE *= *alpha_ptr;

#pragma unroll
    for (int mt = 0; mt < MT; mt++) {
#pragma unroll
        for (int r = 0; r < 2; r++) {
            const int gm = m0 + wm + mt * 16 + g + r * 8;
            if (gm >= M) continue;
            float* crow = Cb + (long long)gm * ldc;
#pragma unroll
            for (int nt = 0; nt < 4; nt++) {
                const int gn = n0 + wn + nt * 8 + tg * 2;
                if (gn >= N) continue;
                float x = c[mt][nt][r * 2 + 0] * aE;
                float y = c[mt][nt][r * 2 + 1] * aE;
                if (bias) { x += bias[gn]; y += bias[gn + 1]; }
                if (beta != 0.f) {
                    float2 p = *(const float2*)(crow + gn);
                    x += beta * p.x; y += beta * p.y;
                }
                if (RND) { x = rndf(x); y = rndf(y); }
                *(float2*)(crow + gn) = make_float2(x, y);
            }
        }
    }
}

#define BIG_SMEM   (4 * (128 + 128) * ASTR * 4)
#define SMALL_SMEM (6 * ( 64 +  64) * ASTR * 4)

// ---------------- elementwise kernels ----------------
__global__ void round_copy(const float* __restrict__ s, float* __restrict__ d, int n4)
{
    int i = blockIdx.x * 256 + threadIdx.x;
    if (i < n4) {
        float4 v = ((const float4*)s)[i];
        v.x = rndf(v.x); v.y = rndf(v.y); v.z = rndf(v.z); v.w = rndf(v.w);
        ((float4*)d)[i] = v;
    }
}

__global__ void build_qkv(const float* __restrict__ Pq, const float* __restrict__ Pk,
                          const float* __restrict__ Pv, const float* __restrict__ Eq,
                          const float* __restrict__ Ek, const float* __restrict__ Ev,
                          const float* __restrict__ rc, const float* __restrict__ rs,
                          const float* __restrict__ nqw, const float* __restrict__ nkw,
                          const float* __restrict__ naqw, const float* __restrict__ nakw,
                          float* __restrict__ Q, float* __restrict__ K, float* __restrict__ Vt)
{
    const int s = blockIdx.x;
    const int h = blockIdx.y;
    const int d = threadIdx.x;

    const float *sq, *sk, *sv, *wq, *wk;
    if (s < S_ENC) {
        const long long off = (long long)s * DIMN + h * HD;
        sq = Eq + off; sk = Ek + off; sv = Ev + off;
        wq = naqw; wk = nakw;
    } else {
        const long long off = (long long)(s - S_ENC) * DIMN + h * HD;
        sq = Pq + off; sk = Pk + off; sv = Pv + off;
        wq = nqw; wk = nkw;
    }
    float q = sq[d], k = sk[d], v = sv[d];

    float ssq = q * q, ssk = k * k;
#pragma unroll
    for (int o = 16; o; o >>= 1) {
        ssq += __shfl_xor_sync(0xffffffffu, ssq, o);
        ssk += __shfl_xor_sync(0xffffffffu, ssk, o);
    }
    __shared__ float shq[4], shk[4];
    const int w = d >> 5;
    if ((d & 31) == 0) { shq[w] = ssq; shk[w] = ssk; }
    __syncthreads();
    const float tq = shq[0] + shq[1] + shq[2] + shq[3];
    const float tk = shk[0] + shk[1] + shk[2] + shk[3];

    const float qn = q * rsqrtf(tq * (1.0f / HD) + 1e-6f) * wq[d];
    const float kn = k * rsqrtf(tk * (1.0f / HD) + 1e-6f) * wk[d];

    const float qp = __shfl_xor_sync(0xffffffffu, qn, 1);
    const float kp = __shfl_xor_sync(0xffffffffu, kn, 1);
    const float qr = (d & 1) ? qp : -qp;
    const float kr = (d & 1) ? kp : -kp;

    const float cc = rc[(long long)s * HD + d];
    const float sn = rs[(long long)s * HD + d];

    const long long o = ((long long)h * SEQ + s) * HD + d;
    Q[o] = rndf(qn * cc + qr * sn);
    K[o] = rndf(kn * cc + kr * sn);
    Vt[((long long)h * HD + d) * SEQ + s] = rndf(v);
}

__global__ void softmax_k(float* __restrict__ S, int ncols)
{
    float* r = S + (long long)blockIdx.x * ncols;
    const int tid = threadIdx.x;
    __shared__ float sh[8];

    float m = -INFINITY;
    for (int c = tid; c < ncols; c += 256) m = fmaxf(m, r[c]);
#pragma unroll
    for (int o = 16; o; o >>= 1) m = fmaxf(m, __shfl_xor_sync(0xffffffffu, m, o));
    if ((tid & 31) == 0) sh[tid >> 5] = m;
    __syncthreads();
    float bm = sh[0];
#pragma unroll
    for (int i = 1; i < 8; i++) bm = fmaxf(bm, sh[i]);
    __syncthreads();

    float sum = 0.f;
    for (int c = tid; c < ncols; c += 256) {
        float e = expf(r[c] - bm);
        r[c] = e;
        sum += e;
    }
#pragma unroll
    for (int o = 16; o; o >>= 1) sum += __shfl_xor_sync(0xffffffffu, sum, o);
    if ((tid & 31) == 0) sh[tid >> 5] = sum;
    __syncthreads();
    float bs = 0.f;
#pragma unroll
    for (int i = 0; i < 8; i++) bs += sh[i];
    const float inv = 1.0f / bs;
    for (int c = tid; c < ncols; c += 256) r[c] = rndf(r[c] * inv);
}

__global__ void mean_k(const float* __restrict__ Vt, float* __restrict__ mean)
{
    const int row = blockIdx.x;
    const float* r = Vt + (long long)row * SEQ;
    const int tid = threadIdx.x;
    float s = 0.f;
    for (int c = tid; c < SEQ; c += 256) s += r[c];
#pragma unroll
    for (int o = 16; o; o >>= 1) s += __shfl_xor_sync(0xffffffffu, s, o);
    __shared__ float sh[8];
    if ((tid & 31) == 0) sh[tid >> 5] = s;
    __syncthreads();
    if (tid == 0) {
        float t = 0.f;
#pragma unroll
        for (int i = 0; i < 8; i++) t += sh[i];
        mean[row] = t * (1.0f / SEQ);
    }
}

__global__ void gemv_out(const float* __restrict__ mean, const float* __restrict__ Wo,
                         const float* __restrict__ bo, float* __restrict__ vec)
{
    const int j = blockIdx.x * 8 + (threadIdx.x >> 5);
    const int lane = threadIdx.x & 31;
    const float* w = Wo + (long long)j * DIMN;
    float s = 0.f;
    for (int d = lane; d < DIMN; d += 32) s += mean[d] * w[d];
#pragma unroll
    for (int o = 16; o; o >>= 1) s += __shfl_xor_sync(0xffffffffu, s, o);
    if (lane == 0) vec[j] = s + bo[j];
}

__global__ void fill_rows(const float* __restrict__ vec, float* __restrict__ out)
{
    const long long i = (long long)blockIdx.x * 256 + threadIdx.x;
    const float4 v = ((const float4*)vec)[i % (DIMN / 4)];
    ((float4*)out)[i] = v;
}

__global__ void reduce_splitk(const float* __restrict__ P, float* __restrict__ D)
{
    const int i = blockIdx.x * 256 + threadIdx.x;
    float s = 0.f;
#pragma unroll
    for (int z = 0; z < KSPLIT; z++) s += P[(size_t)z * CONDN * RANKN + i];
    D[i] = rndf(s);
}

// ---------------- host-side launch helpers ----------------
template <bool RND>
static void gemm_big(const float* A, const float* B, const float* bias, float* C,
                     int M, int N, int K, int lda, int ldb, int ldc,
                     long long sA, long long sB, long long sC, int batch,
                     float alpha, const float* aptr, float beta)
{
    dim3 gdim((N + 127) / 128, (M + 127) / 128, batch);
    gemm_tf32<128, 128, 256, 4, 4, 2, RND><<<gdim, 256, BIG_SMEM>>>(
        A, B, bias, C, M, N, K, lda, ldb, ldc, sA, sB, sC, alpha, aptr, beta);
}

template <bool RND>
static void gemm_small(const float* A, const float* B, const float* bias, float* C,
                       int M, int N, int K, int lda, int ldb, int ldc,
                       long long sA, long long sB, long long sC, int batch,
                       float alpha, const float* aptr, float beta)
{
    dim3 gdim((N + 63) / 64, (M + 63) / 64, batch);
    gemm_tf32<64, 64, 128, 6, 2, 3, RND><<<gdim, 128, SMALL_SMEM>>>(
        A, B, bias, C, M, N, K, lda, ldb, ldc, sA, sB, sC, alpha, aptr, beta);
}

static void rcopy(const float* s, float* d, long long n)
{
    int n4 = (int)(n / 4);
    round_copy<<<(n4 + 255) / 256, 256>>>(s, d, n4);
}

extern "C" void kernel_launch(void* const* d_in, const int* in_sizes, int n_in,
                              void* d_out, int out_size)
{
    const float* hidden = (const float*)d_in[0];
    const float* enc    = (const float*)d_in[1];
    const float* rc     = (const float*)d_in[2];
    const float* rs     = (const float*)d_in[3];
    const float* Wq  = (const float*)d_in[4];
    const float* Wk  = (const float*)d_in[5];
    const float* Wv  = (const float*)d_in[6];
    const float* Wqa = (const float*)d_in[7];
    const float* Wka = (const float*)d_in[8];
    const float* Wva = (const float*)d_in[9];
    const float* Wo  = (const float*)d_in[10];
    const float* Woa = (const float*)d_in[11];
    const float* bq  = (const float*)d_in[12];
    const float* bk  = (const float*)d_in[13];
    const float* bv  = (const float*)d_in[14];
    const float* bqa = (const float*)d_in[15];
    const float* bka = (const float*)d_in[16];
    const float* bva = (const float*)d_in[17];
    const float* bo  = (const float*)d_in[18];
    const float* boa = (const float*)d_in[19];
    const float* nqw  = (const float*)d_in[20];
    const float* nkw  = (const float*)d_in[21];
    const float* naqw = (const float*)d_in[22];
    const float* nakw = (const float*)d_in[23];
    const float* qd = (const float*)d_in[24];
    const float* kd = (const float*)d_in[25];
    const float* vd = (const float*)d_in[26];
    const float* qu = (const float*)d_in[27];
    const float* ku = (const float*)d_in[28];
    const float* vu = (const float*)d_in[29];
    const float* lw = (const float*)d_in[30];

    float *Pq, *Pk, *Pv, *Eq, *Ek, *Ev, *Dt, *DtP, *Q, *K, *Vt, *SA, *SB, *AO, *mean, *vec;
    float *rh, *re, *rWq, *rWk, *rWv, *rWqa, *rWka, *rWva, *rWo, *rWoa, *rdn, *rup;
    cudaGetSymbolAddress((void**)&Pq, g_Pq);
    cudaGetSymbolAddress((void**)&Pk, g_Pk);
    cudaGetSymbolAddress((void**)&Pv, g_Pv);
    cudaGetSymbolAddress((void**)&Eq, g_Eq);
    cudaGetSymbolAddress((void**)&Ek, g_Ek);
    cudaGetSymbolAddress((void**)&Ev, g_Ev);
    cudaGetSymbolAddress((void**)&Dt, g_Dt);
    cudaGetSymbolAddress((void**)&DtP, g_DtP);
    cudaGetSymbolAddress((void**)&Q,  g_Q);
    cudaGetSymbolAddress((void**)&K,  g_K);
    cudaGetSymbolAddress((void**)&Vt, g_Vt);
    cudaGetSymbolAddress((void**)&SA, g_SA);
    cudaGetSymbolAddress((void**)&SB, g_SB);
    cudaGetSymbolAddress((void**)&AO, g_AO);
    cudaGetSymbolAddress((void**)&mean, g_mean);
    cudaGetSymbolAddress((void**)&vec,  g_vec);
    cudaGetSymbolAddress((void**)&rh,  g_rh);
    cudaGetSymbolAddress((void**)&re,  g_re);
    cudaGetSymbolAddress((void**)&rWq, g_rWq);
    cudaGetSymbolAddress((void**)&rWk, g_rWk);
    cudaGetSymbolAddress((void**)&rWv, g_rWv);
    cudaGetSymbolAddress((void**)&rWqa, g_rWqa);
    cudaGetSymbolAddress((void**)&rWka, g_rWka);
    cudaGetSymbolAddress((void**)&rWva, g_rWva);
    cudaGetSymbolAddress((void**)&rWo,  g_rWo);
    cudaGetSymbolAddress((void**)&rWoa, g_rWoa);
    cudaGetSymbolAddress((void**)&rdn,  g_rdn);
    cudaGetSymbolAddress((void**)&rup,  g_rup);

    float* out = (float*)d_out;

    // REQUIRED: opt-in to >48KB dynamic smem for every GEMM instantiation.
    // (Dropping these made every GEMM launch fail -> graph capture poisoned.)
    cudaFuncSetAttribute(gemm_tf32<128, 128, 256, 4, 4, 2, false>,
                         cudaFuncAttributeMaxDynamicSharedMemorySize, BIG_SMEM);
    cudaFuncSetAttribute(gemm_tf32<128, 128, 256, 4, 4, 2, true>,
                         cudaFuncAttributeMaxDynamicSharedMemorySize, BIG_SMEM);
    cudaFuncSetAttribute(gemm_tf32<64, 64, 128, 6, 2, 3, false>,
                         cudaFuncAttributeMaxDynamicSharedMemorySize, SMALL_SMEM);
    cudaFuncSetAttribute(gemm_tf32<64, 64, 128, 6, 2, 3, true>,
                         cudaFuncAttributeMaxDynamicSharedMemorySize, SMALL_SMEM);

    // 0) RNA-round all primary GEMM operands once
    rcopy(hidden, rh, (long long)S_HID * DIMN);
    rcopy(enc,    re, (long long)S_ENC * DIMN);
    rcopy(Wq,  rWq,  (long long)DIMN * DIMN);
    rcopy(Wk,  rWk,  (long long)DIMN * DIMN);
    rcopy(Wv,  rWv,  (long long)DIMN * DIMN);
    rcopy(Wqa, rWqa, (long long)DIMN * DIMN);
    rcopy(Wka, rWka, (long long)DIMN * DIMN);
    rcopy(Wva, rWva, (long long)DIMN * DIMN);
    rcopy(Wo,  rWo,  (long long)DIMN * DIMN);
    rcopy(Woa, rWoa, (long long)DIMN * DIMN);
    rcopy(qd, rdn + 0 * (long long)RANKN * DIMN, (long long)RANKN * DIMN);
    rcopy(kd, rdn + 1 * (long long)RANKN * DIMN, (long long)RANKN * DIMN);
    rcopy(vd, rdn + 2 * (long long)RANKN * DIMN, (long long)RANKN * DIMN);
    rcopy(qu, rup + 0 * (long long)DIMN * RANKN, (long long)DIMN * RANKN);
    rcopy(ku, rup + 1 * (long long)DIMN * RANKN, (long long)DIMN * RANKN);
    rcopy(vu, rup + 2 * (long long)DIMN * RANKN, (long long)DIMN * RANKN);

    // 1) image-side base projections: P = hidden @ W^T + b
    gemm_big<false>(rh, rWq, bq, Pq, S_HID, DIMN, DIMN, DIMN, DIMN, DIMN, 0, 0, 0, 1, 1.f, nullptr, 0.f);
    gemm_big<false>(rh, rWk, bk, Pk, S_HID, DIMN, DIMN, DIMN, DIMN, DIMN, 0, 0, 0, 1, 1.f, nullptr, 0.f);
    gemm_big<false>(rh, rWv, bv, Pv, S_HID, DIMN, DIMN, DIMN, DIMN, DIMN, 0, 0, 0, 1, 1.f, nullptr, 0.f);

    // 2) encoder projections (M=512 -> SMALL)
    gemm_small<false>(re, rWqa, bqa, Eq, S_ENC, DIMN, DIMN, DIMN, DIMN, DIMN, 0, 0, 0, 1, 1.f, nullptr, 0.f);
    gemm_small<false>(re, rWka, bka, Ek, S_ENC, DIMN, DIMN, DIMN, DIMN, DIMN, 0, 0, 0, 1, 1.f, nullptr, 0.f);
    gemm_small<false>(re, rWva, bva, Ev, S_ENC, DIMN, DIMN, DIMN, DIMN, DIMN, 0, 0, 0, 1, 1.f, nullptr, 0.f);

    // 3) LoRA: only hidden rows [2048,3072) survive; sc = lora_w[0]*ALPHA/RANK = lora_w[0]
    for (int i = 0; i < 3; i++) {
        const float* dn = rdn + (long long)i * RANKN * DIMN;
        const float* up = rup + (long long)i * DIMN * RANKN;
        float* P = (i == 0) ? Pq : (i == 1) ? Pk : Pv;
        gemm_small<false>(rh + (long long)BLOCKL * DIMN, dn, nullptr, DtP,
                          CONDN, RANKN, DIMN / KSPLIT, DIMN, DIMN, RANKN,
                          DIMN / KSPLIT, DIMN / KSPLIT, (long long)CONDN * RANKN, KSPLIT,
                          1.f, nullptr, 0.f);
        reduce_splitk<<<(CONDN * RANKN) / 256, 256>>>(DtP, Dt);
        gemm_small<false>(Dt, up, nullptr, P + (long long)BLOCKL * DIMN,
                          CONDN, DIMN, RANKN, RANKN, RANKN, DIMN, 0, 0, 0, 1, 1.f, lw, 1.f);
    }

    // 4) heads + RMSNorm + RoPE + concat; Q/K/Vt written tf32-rounded
    build_qkv<<<dim3(SEQ, HEADS), HD>>>(Pq, Pk, Pv, Eq, Ek, Ev, rc, rs,
                                        nqw, nkw, naqw, nakw, Q, K, Vt);

    // 5) block A: encoder queries vs full keys
    gemm_big<false>(Q, K, nullptr, SA, S_ENC, SEQ, HD, HD, HD, SEQ,
                    (long long)SEQ * HD, (long long)SEQ * HD, (long long)S_ENC * SEQ, HEADS,
                    ATTN_SCALE, nullptr, 0.f);
    softmax_k<<<HEADS * S_ENC, 256>>>(SA, SEQ);
    gemm_small<true>(SA, Vt, nullptr, AO, S_ENC, HD, SEQ, SEQ, SEQ, DIMN,
                     (long long)S_ENC * SEQ, (long long)HD * SEQ, HD, HEADS, 1.f, nullptr, 0.f);

    // 6) block B: cond queries vs cond keys
    gemm_big<false>(Q + (long long)S_ENC * HD, K + (long long)S_ENC * HD, nullptr, SB,
                    CONDN, CONDN, HD, HD, HD, CONDN,
                    (long long)SEQ * HD, (long long)SEQ * HD, (long long)CONDN * CONDN, HEADS,
                    ATTN_SCALE, nullptr, 0.f);
    softmax_k<<<HEADS * CONDN, 256>>>(SB, CONDN);
    gemm_small<true>(SB, Vt + S_ENC, nullptr, AO + (long long)S_ENC * DIMN,
                     CONDN, HD, CONDN, CONDN, SEQ, DIMN,
                     (long long)CONDN * CONDN, (long long)HD * SEQ, HD, HEADS, 1.f, nullptr, 0.f);

    // 7) fully-masked rows -> uniform softmax -> mean of V; one out-proj row
    mean_k<<<DIMN, 256>>>(Vt, mean);
    gemv_out<<<DIMN / 8, 256>>>(mean, Wo, bo, vec);

    // 8) output projections
    gemm_big<false>(AO + (long long)S_ENC * DIMN, rWo, bo, out,
                    CONDN, DIMN, DIMN, DIMN, DIMN, DIMN, 0, 0, 0, 1, 1.f, nullptr, 0.f);
    fill_rows<<<(NROWS_C * (DIMN / 4)) / 256, 256>>>(vec, out + (long long)CONDN * DIMN);
    gemm_small<false>(AO, rWoa, boa, out + (long long)S_HID * DIMN,
                      S_ENC, DIMN, DIMN, DIMN, DIMN, DIMN, 0, 0, 0, 1, 1.f, nullptr, 0.f);
}